// round 5
// baseline (speedup 1.0000x reference)
#include <cuda_runtime.h>
#include <math.h>
#include <stdint.h>

#define BATCH 128
#define NTOK  1024
#define DIM   512
#define NSLOT 100
#define ROWS  (BATCH*NSLOT)      /* 12800 */
#define BT    (BATCH*NTOK)       /* 131072 */
#define NELEM (ROWS*DIM)         /* 6553600 */

// ---------------- scratch (static device globals; no allocation) ----------------
__device__ float g_slots[ROWS*DIM];
__device__ float g_q[ROWS*DIM];
__device__ float g_k[(size_t)BT*DIM];
__device__ float g_attn[(size_t)ROWS*NTOK];
__device__ float g_upd[ROWS*DIM];
__device__ float g_gi[(size_t)ROWS*3*DIM];
__device__ float g_gh[(size_t)ROWS*3*DIM];
__device__ float g_losspart[ROWS];

// ---------------- threefry-2x32 (JAX-exact core) ----------------
__device__ __forceinline__ uint32_t rotl32(uint32_t x, int r) {
    return (x << r) | (x >> (32 - r));
}

__device__ __forceinline__ void threefry2x32(uint32_t k0, uint32_t k1,
                                             uint32_t& x0, uint32_t& x1) {
    uint32_t k2 = k0 ^ k1 ^ 0x1BD11BDAu;
    x0 += k0; x1 += k1;
#define TF_RND(r) { x0 += x1; x1 = rotl32(x1, r); x1 ^= x0; }
    TF_RND(13) TF_RND(15) TF_RND(26) TF_RND(6)   x0 += k1; x1 += k2 + 1u;
    TF_RND(17) TF_RND(29) TF_RND(16) TF_RND(24)  x0 += k2; x1 += k0 + 2u;
    TF_RND(13) TF_RND(15) TF_RND(26) TF_RND(6)   x0 += k0; x1 += k1 + 3u;
    TF_RND(17) TF_RND(29) TF_RND(16) TF_RND(24)  x0 += k1; x1 += k2 + 4u;
    TF_RND(13) TF_RND(15) TF_RND(26) TF_RND(6)   x0 += k2; x1 += k0 + 5u;
#undef TF_RND
}

__device__ __forceinline__ float bits_to_normal(uint32_t b) {
    // JAX: f in [0,1); u = f*(hi-lo)+lo with lo=nextafter(-1,0); clamp; sqrt(2)*erfinv
    float f  = __uint_as_float((b >> 9) | 0x3f800000u) - 1.0f;
    const float lo = -0.99999994f;
    float u = f * 2.0f + lo;            // (hi-lo) rounds to 2.0f in f32, matching JAX
    u = fmaxf(lo, u);
    return 1.41421356f * erfinvf(u);
}

// Partitionable threefry (JAX >= 0.4.30 default): element i uses 64-bit counter i,
// fed as (x0, x1) = (i >> 32, i & 0xffffffff) = (0, i) here; the 32-bit draw is
// the XOR-fold of the two threefry output words.
__global__ void init_slots_kernel(const float* __restrict__ mu,
                                  const float* __restrict__ sigma) {
    int i = blockIdx.x * blockDim.x + threadIdx.x;
    if (i >= NELEM) return;
    uint32_t x0 = 0u, x1 = (uint32_t)i;
    threefry2x32(0u, 1u, x0, x1);
    float nrm = bits_to_normal(x0 ^ x1);
    int c = i & (DIM - 1);
    g_slots[i] = fmaf(fabsf(sigma[c]), nrm, mu[c]);
}

// ---------------- GEMM NT: C[M,N] = scale * A[M,K] @ B[N,K]^T + bias ----------------
__global__ __launch_bounds__(256)
void gemm_nt(const float* __restrict__ A, const float* __restrict__ Bm,
             const float* __restrict__ bias, float* __restrict__ C,
             int M, int N, int K, float scale,
             long long sA, long long sB, long long sC) {
    A  += (long long)blockIdx.z * sA;
    Bm += (long long)blockIdx.z * sB;
    C  += (long long)blockIdx.z * sC;
    __shared__ float As[16][65];
    __shared__ float Bs[16][65];
    int tid = threadIdx.x;
    int tx = tid & 15, ty = tid >> 4;
    int bm = blockIdx.y << 6, bn = blockIdx.x << 6;
    float acc[4][4] = {};
    for (int k0 = 0; k0 < K; k0 += 16) {
#pragma unroll
        for (int i = 0; i < 4; ++i) {
            int e = tid + (i << 8);
            int r = e >> 4, kk = e & 15;
            int ar = bm + r;
            As[kk][r] = (ar < M) ? __ldg(A + (long long)ar * K + k0 + kk) : 0.f;
            int br = bn + r;
            Bs[kk][r] = (br < N) ? __ldg(Bm + (long long)br * K + k0 + kk) : 0.f;
        }
        __syncthreads();
#pragma unroll
        for (int kk = 0; kk < 16; ++kk) {
            float a[4], b[4];
#pragma unroll
            for (int i = 0; i < 4; ++i) a[i] = As[kk][(ty << 2) + i];
#pragma unroll
            for (int j = 0; j < 4; ++j) b[j] = Bs[kk][(tx << 2) + j];
#pragma unroll
            for (int i = 0; i < 4; ++i)
#pragma unroll
                for (int j = 0; j < 4; ++j)
                    acc[i][j] = fmaf(a[i], b[j], acc[i][j]);
        }
        __syncthreads();
    }
#pragma unroll
    for (int i = 0; i < 4; ++i) {
        int row = bm + (ty << 2) + i;
        if (row >= M) continue;
#pragma unroll
        for (int j = 0; j < 4; ++j) {
            int col = bn + (tx << 2) + j;
            if (col < N) {
                float v = acc[i][j] * scale;
                if (bias) v += bias[col];
                C[(long long)row * N + col] = v;
            }
        }
    }
}

// ---------------- GEMM NN: C[M,N] = scale * A[M,K] @ B[K,N] ----------------
__global__ __launch_bounds__(256)
void gemm_nn(const float* __restrict__ A, const float* __restrict__ Bm,
             float* __restrict__ C,
             int M, int N, int K, float scale,
             long long sA, long long sB, long long sC) {
    A  += (long long)blockIdx.z * sA;
    Bm += (long long)blockIdx.z * sB;
    C  += (long long)blockIdx.z * sC;
    __shared__ float As[16][65];
    __shared__ float Bs[16][65];
    int tid = threadIdx.x;
    int tx = tid & 15, ty = tid >> 4;
    int bm = blockIdx.y << 6, bn = blockIdx.x << 6;
    float acc[4][4] = {};
    for (int k0 = 0; k0 < K; k0 += 16) {
#pragma unroll
        for (int i = 0; i < 4; ++i) {
            int e = tid + (i << 8);
            { // A tile 64 rows x 16 k
                int r = e >> 4, kk = e & 15;
                int ar = bm + r;
                As[kk][r] = (ar < M) ? __ldg(A + (long long)ar * K + k0 + kk) : 0.f;
            }
            { // B tile 16 k x 64 cols (coalesced over cols)
                int kk = e >> 6, c = e & 63;
                int bc = bn + c;
                Bs[kk][c] = (bc < N) ? __ldg(Bm + (long long)(k0 + kk) * N + bc) : 0.f;
            }
        }
        __syncthreads();
#pragma unroll
        for (int kk = 0; kk < 16; ++kk) {
            float a[4], b[4];
#pragma unroll
            for (int i = 0; i < 4; ++i) a[i] = As[kk][(ty << 2) + i];
#pragma unroll
            for (int j = 0; j < 4; ++j) b[j] = Bs[kk][(tx << 2) + j];
#pragma unroll
            for (int i = 0; i < 4; ++i)
#pragma unroll
                for (int j = 0; j < 4; ++j)
                    acc[i][j] = fmaf(a[i], b[j], acc[i][j]);
        }
        __syncthreads();
    }
#pragma unroll
    for (int i = 0; i < 4; ++i) {
        int row = bm + (ty << 2) + i;
        if (row >= M) continue;
#pragma unroll
        for (int j = 0; j < 4; ++j) {
            int col = bn + (tx << 2) + j;
            if (col < N)
                C[(long long)row * N + col] = acc[i][j] * scale;
        }
    }
}

// ---------------- softmax over rows of length 1024 ----------------
__global__ __launch_bounds__(256)
void softmax_rows(float* __restrict__ attn) {
    long long row = blockIdx.x;
    float* p = attn + row * NTOK;
    int t = threadIdx.x;
    __shared__ float red[8];
    __shared__ float bc;
    float v[4];
    float m = -INFINITY;
#pragma unroll
    for (int i = 0; i < 4; ++i) { v[i] = p[t + i * 256]; m = fmaxf(m, v[i]); }
#pragma unroll
    for (int o = 16; o; o >>= 1) m = fmaxf(m, __shfl_xor_sync(0xffffffffu, m, o));
    if ((t & 31) == 0) red[t >> 5] = m;
    __syncthreads();
    if (t == 0) {
        float mm = red[0];
#pragma unroll
        for (int i = 1; i < 8; ++i) mm = fmaxf(mm, red[i]);
        bc = mm;
    }
    __syncthreads();
    m = bc;
    float s = 0.f;
#pragma unroll
    for (int i = 0; i < 4; ++i) { v[i] = expf(v[i] - m); s += v[i]; }
#pragma unroll
    for (int o = 16; o; o >>= 1) s += __shfl_xor_sync(0xffffffffu, s, o);
    __syncthreads();
    if ((t & 31) == 0) red[t >> 5] = s;
    __syncthreads();
    if (t == 0) {
        float ss = 0.f;
#pragma unroll
        for (int i = 0; i < 8; ++i) ss += red[i];
        bc = 1.0f / ss;
    }
    __syncthreads();
    float inv = bc;
#pragma unroll
    for (int i = 0; i < 4; ++i) p[t + i * 256] = v[i] * inv;
}

// ---------------- GRU gate fusion (slots updated in place) ----------------
__global__ __launch_bounds__(256)
void gru_kernel(float* __restrict__ slots,
                const float* __restrict__ gi, const float* __restrict__ gh) {
    long long idx = (long long)blockIdx.x * 256 + threadIdx.x;
    if (idx >= (long long)ROWS * DIM) return;
    long long r = idx >> 9;
    int c = (int)(idx & (DIM - 1));
    const float* gir = gi + r * (3 * DIM);
    const float* ghr = gh + r * (3 * DIM);
    float ir = gir[c], iz = gir[c + DIM], inn = gir[c + 2 * DIM];
    float hr = ghr[c], hz = ghr[c + DIM], hn  = ghr[c + 2 * DIM];
    float rg = 1.0f / (1.0f + expf(-(ir + hr)));
    float z  = 1.0f / (1.0f + expf(-(iz + hz)));
    float nn = tanhf(inn + rg * hn);
    float h = slots[idx];
    slots[idx] = (1.0f - z) * nn + z * h;
}

// ---------------- finalize: out[row]=sum_d upd; losspart[row]=sum_n attn ----------------
__global__ __launch_bounds__(256)
void finalize_kernel(const float* __restrict__ upd, const float* __restrict__ attn,
                     float* __restrict__ out, float* __restrict__ lp) {
    long long row = blockIdx.x;
    int t = threadIdx.x;
    __shared__ float sh[256];
    const float* ur = upd + row * DIM;
    float s = ur[t] + ur[t + 256];
    sh[t] = s; __syncthreads();
    for (int o = 128; o; o >>= 1) { if (t < o) sh[t] += sh[t + o]; __syncthreads(); }
    if (t == 0) out[row] = sh[0];
    __syncthreads();
    const float* ar = attn + row * NTOK;
    float a = ar[t] + ar[t + 256] + ar[t + 512] + ar[t + 768];
    sh[t] = a; __syncthreads();
    for (int o = 128; o; o >>= 1) { if (t < o) sh[t] += sh[t + o]; __syncthreads(); }
    if (t == 0) lp[row] = sh[0];
}

__global__ __launch_bounds__(256)
void loss_write_kernel(const float* __restrict__ lp, float* __restrict__ out,
                       int out_size) {
    if (out_size <= ROWS) return;
    int t = threadIdx.x;
    __shared__ float sh[256];
    float s = 0.f;
    for (int i = t; i < ROWS; i += 256) s += lp[i];
    sh[t] = s; __syncthreads();
    for (int o = 128; o; o >>= 1) { if (t < o) sh[t] += sh[t + o]; __syncthreads(); }
    if (t == 0) out[ROWS] = sh[0] * (1.0f / ((float)ROWS * (float)NTOK));
}

// ---------------- host ----------------
extern "C" void kernel_launch(void* const* d_in, const int* in_sizes, int n_in,
                              void* d_out, int out_size) {
    const float* inputs   = (const float*)d_in[0];
    const float* inputs_x = (const float*)d_in[1];
    const float* mu       = (const float*)d_in[2];
    const float* sigma    = (const float*)d_in[3];
    const float* qw       = (const float*)d_in[4];
    const float* qb       = (const float*)d_in[5];
    const float* kw       = (const float*)d_in[6];
    const float* kb       = (const float*)d_in[7];
    const float* wih      = (const float*)d_in[8];
    const float* whh      = (const float*)d_in[9];
    const float* bih      = (const float*)d_in[10];
    const float* bhh      = (const float*)d_in[11];
    float* out = (float*)d_out;

    float *slots, *q, *k, *attn, *upd, *gi, *gh, *lp;
    cudaGetSymbolAddress((void**)&slots, g_slots);
    cudaGetSymbolAddress((void**)&q,     g_q);
    cudaGetSymbolAddress((void**)&k,     g_k);
    cudaGetSymbolAddress((void**)&attn,  g_attn);
    cudaGetSymbolAddress((void**)&upd,   g_upd);
    cudaGetSymbolAddress((void**)&gi,    g_gi);
    cudaGetSymbolAddress((void**)&gh,    g_gh);
    cudaGetSymbolAddress((void**)&lp,    g_losspart);

    const float dot_scale = 0.04419417382f;   // 512^-0.5
    const float upd_scale = 1.0f / 512.0f;

    // slots = mu + |sigma| * threefry_normal (partitionable counter scheme)
    init_slots_kernel<<<(NELEM + 255) / 256, 256>>>(mu, sigma);

    // k = inputs @ kw^T + kb   [131072, 512]
    gemm_nt<<<dim3(DIM / 64, BT / 64, 1), 256>>>(inputs, kw, kb, k,
                                                 BT, DIM, DIM, 1.0f, 0, 0, 0);

    for (int it = 0; it < 3; ++it) {
        // q = slots @ qw^T + qb  [12800, 512]
        gemm_nt<<<dim3(DIM / 64, ROWS / 64, 1), 256>>>(slots, qw, qb, q,
                                                       ROWS, DIM, DIM, 1.0f, 0, 0, 0);
        // dots = scale * q @ k^T  per batch: [100,1024]
        gemm_nt<<<dim3(NTOK / 64, 2, BATCH), 256>>>(q, k, nullptr, attn,
                                                    NSLOT, NTOK, DIM, dot_scale,
                                                    (long long)NSLOT * DIM,
                                                    (long long)NTOK * DIM,
                                                    (long long)NSLOT * NTOK);
        // softmax over n
        softmax_rows<<<ROWS, 256>>>(attn);
        // updates = (attn @ x) / d  per batch: [100,512]
        gemm_nn<<<dim3(DIM / 64, 2, BATCH), 256>>>(attn, inputs_x, upd,
                                                   NSLOT, DIM, NTOK, upd_scale,
                                                   (long long)NSLOT * NTOK,
                                                   (long long)NTOK * DIM,
                                                   (long long)NSLOT * DIM);
        // gi = upd @ wih^T + bih ; gh = slots @ whh^T + bhh   [12800, 1536]
        gemm_nt<<<dim3(3 * DIM / 64, ROWS / 64, 1), 256>>>(upd, wih, bih, gi,
                                                           ROWS, 3 * DIM, DIM, 1.0f, 0, 0, 0);
        gemm_nt<<<dim3(3 * DIM / 64, ROWS / 64, 1), 256>>>(slots, whh, bhh, gh,
                                                           ROWS, 3 * DIM, DIM, 1.0f, 0, 0, 0);
        // slots = GRU(upd, slots)
        gru_kernel<<<(ROWS * DIM + 255) / 256, 256>>>(slots, gi, gh);
    }

    finalize_kernel<<<ROWS, 256>>>(upd, attn, out, lp);
    loss_write_kernel<<<1, 256>>>(lp, out, out_size);
}

// round 6
// speedup vs baseline: 3.8302x; 3.8302x over previous
#include <cuda_runtime.h>
#include <math.h>
#include <stdint.h>

#define BATCH 128
#define NTOK  1024
#define DIM   512
#define NSLOT 100
#define ROWS  (BATCH*NSLOT)      /* 12800 */
#define BT    (BATCH*NTOK)       /* 131072 */
#define NELEM (ROWS*DIM)         /* 6553600 */

// ---------------- scratch (static device globals; no allocation) ----------------
__device__ float g_slots[ROWS*DIM];
__device__ float g_q[ROWS*DIM];
__device__ float g_k[(size_t)BT*DIM];
__device__ float g_attn[(size_t)ROWS*NTOK];
__device__ float g_upd[ROWS*DIM];
__device__ float g_gi[(size_t)ROWS*3*DIM];
__device__ float g_gh[(size_t)ROWS*3*DIM];
__device__ float g_losspart[ROWS];

// ---------------- threefry-2x32 (JAX-exact core) ----------------
__device__ __forceinline__ uint32_t rotl32(uint32_t x, int r) {
    return (x << r) | (x >> (32 - r));
}

__device__ __forceinline__ void threefry2x32(uint32_t k0, uint32_t k1,
                                             uint32_t& x0, uint32_t& x1) {
    uint32_t k2 = k0 ^ k1 ^ 0x1BD11BDAu;
    x0 += k0; x1 += k1;
#define TF_RND(r) { x0 += x1; x1 = rotl32(x1, r); x1 ^= x0; }
    TF_RND(13) TF_RND(15) TF_RND(26) TF_RND(6)   x0 += k1; x1 += k2 + 1u;
    TF_RND(17) TF_RND(29) TF_RND(16) TF_RND(24)  x0 += k2; x1 += k0 + 2u;
    TF_RND(13) TF_RND(15) TF_RND(26) TF_RND(6)   x0 += k0; x1 += k1 + 3u;
    TF_RND(17) TF_RND(29) TF_RND(16) TF_RND(24)  x0 += k1; x1 += k2 + 4u;
    TF_RND(13) TF_RND(15) TF_RND(26) TF_RND(6)   x0 += k2; x1 += k0 + 5u;
#undef TF_RND
}

__device__ __forceinline__ float bits_to_normal(uint32_t b) {
    float f  = __uint_as_float((b >> 9) | 0x3f800000u) - 1.0f;
    const float lo = -0.99999994f;
    float u = f * 2.0f + lo;
    u = fmaxf(lo, u);
    return 1.41421356f * erfinvf(u);
}

__global__ void init_slots_kernel(const float* __restrict__ mu,
                                  const float* __restrict__ sigma) {
    int i = blockIdx.x * blockDim.x + threadIdx.x;
    if (i >= NELEM) return;
    uint32_t x0 = 0u, x1 = (uint32_t)i;
    threefry2x32(0u, 1u, x0, x1);
    float nrm = bits_to_normal(x0 ^ x1);
    int c = i & (DIM - 1);
    g_slots[i] = fmaf(fabsf(sigma[c]), nrm, mu[c]);
}

// ---------------- tf32 helpers ----------------
__device__ __forceinline__ uint32_t f2tf(float f) {
    uint32_t r;
    asm("cvt.rna.tf32.f32 %0, %1;" : "=r"(r) : "f"(f));
    return r;
}

__device__ __forceinline__ void mma_tf32(float d[4],
                                         uint32_t a0, uint32_t a1, uint32_t a2, uint32_t a3,
                                         uint32_t b0, uint32_t b1) {
    asm volatile(
        "mma.sync.aligned.m16n8k8.row.col.f32.tf32.tf32.f32 "
        "{%0,%1,%2,%3}, {%4,%5,%6,%7}, {%8,%9}, {%0,%1,%2,%3};"
        : "+f"(d[0]), "+f"(d[1]), "+f"(d[2]), "+f"(d[3])
        : "r"(a0), "r"(a1), "r"(a2), "r"(a3), "r"(b0), "r"(b1));
}

// ---------------- tf32 tensor-core GEMM ----------------
// C[M,N] = scale * A[M,K] @ op(B) + bias
// TRANSB=true : B is [N,K] row-major (NT)
// TRANSB=false: B is [K,N] row-major (NN)
// Block tile 128x64, K-chunk 32; 8 warps in 4(m) x 2(n), warp tile 32x32.
// Requirements: K % 32 == 0, N % 64 == 0; M guarded.
template <bool TRANSB>
__global__ __launch_bounds__(256)
void gemm_tf32(const float* __restrict__ A, const float* __restrict__ B,
               const float* __restrict__ bias, float* __restrict__ C,
               int M, int N, int K, float scale,
               long long sA, long long sB, long long sC) {
    A += (long long)blockIdx.z * sA;
    B += (long long)blockIdx.z * sB;
    C += (long long)blockIdx.z * sC;
    const int bm = blockIdx.y << 7;   // *128
    const int bn = blockIdx.x << 6;   // *64

    __shared__ uint32_t As[128][36];  // padded: fragment LDS is bank-conflict-free
    __shared__ uint32_t Bs[64][36];   // stored as [n][k]

    const int tid  = threadIdx.x;
    const int lane = tid & 31;
    const int wid  = tid >> 5;
    const int wm = (wid & 3) << 5;    // warp m offset 0..96
    const int wn = (wid >> 2) << 5;   // warp n offset 0/32
    const int g  = lane >> 2;         // group id 0..7
    const int tg = lane & 3;          // thread-in-group 0..3

    float acc[2][4][4];
#pragma unroll
    for (int mt = 0; mt < 2; ++mt)
#pragma unroll
        for (int nt = 0; nt < 4; ++nt)
#pragma unroll
            for (int e = 0; e < 4; ++e) acc[mt][nt][e] = 0.f;

    for (int k0 = 0; k0 < K; k0 += 32) {
        // ---- load A tile 128x32 (4 float4 per thread) ----
#pragma unroll
        for (int i = 0; i < 4; ++i) {
            int idx = tid + (i << 8);       // 0..1023
            int row = idx >> 3;
            int c4  = (idx & 7) << 2;
            float4 v;
            if (bm + row < M)
                v = *(const float4*)(A + (long long)(bm + row) * K + k0 + c4);
            else
                v = make_float4(0.f, 0.f, 0.f, 0.f);
            uint4 t;
            t.x = f2tf(v.x); t.y = f2tf(v.y); t.z = f2tf(v.z); t.w = f2tf(v.w);
            *(uint4*)&As[row][c4] = t;
        }
        // ---- load B tile -> Bs[n][k] ----
        if (TRANSB) {
#pragma unroll
            for (int i = 0; i < 2; ++i) {
                int idx = tid + (i << 8);   // 0..511
                int row = idx >> 3;         // n 0..63
                int c4  = (idx & 7) << 2;   // k
                float4 v = *(const float4*)(B + (long long)(bn + row) * K + k0 + c4);
                uint4 t;
                t.x = f2tf(v.x); t.y = f2tf(v.y); t.z = f2tf(v.z); t.w = f2tf(v.w);
                *(uint4*)&Bs[row][c4] = t;
            }
        } else {
#pragma unroll
            for (int i = 0; i < 2; ++i) {
                int idx = tid + (i << 8);   // 0..511
                int kr  = idx >> 4;         // k 0..31
                int nc  = (idx & 15) << 2;  // n 0..60
                float4 v = *(const float4*)(B + (long long)(k0 + kr) * N + bn + nc);
                Bs[nc + 0][kr] = f2tf(v.x);
                Bs[nc + 1][kr] = f2tf(v.y);
                Bs[nc + 2][kr] = f2tf(v.z);
                Bs[nc + 3][kr] = f2tf(v.w);
            }
        }
        __syncthreads();

#pragma unroll
        for (int ks = 0; ks < 4; ++ks) {
            const int k8 = ks << 3;
            uint32_t a[2][4], b[4][2];
#pragma unroll
            for (int mt = 0; mt < 2; ++mt) {
                int r = wm + (mt << 4);
                a[mt][0] = As[r + g][k8 + tg];
                a[mt][1] = As[r + 8 + g][k8 + tg];
                a[mt][2] = As[r + g][k8 + tg + 4];
                a[mt][3] = As[r + 8 + g][k8 + tg + 4];
            }
#pragma unroll
            for (int nt = 0; nt < 4; ++nt) {
                int c = wn + (nt << 3);
                b[nt][0] = Bs[c + g][k8 + tg];
                b[nt][1] = Bs[c + g][k8 + tg + 4];
            }
#pragma unroll
            for (int mt = 0; mt < 2; ++mt)
#pragma unroll
                for (int nt = 0; nt < 4; ++nt)
                    mma_tf32(acc[mt][nt], a[mt][0], a[mt][1], a[mt][2], a[mt][3],
                             b[nt][0], b[nt][1]);
        }
        __syncthreads();
    }

    // ---- epilogue ----
#pragma unroll
    for (int mt = 0; mt < 2; ++mt) {
#pragma unroll
        for (int nt = 0; nt < 4; ++nt) {
            int col = bn + wn + (nt << 3) + (tg << 1);
            float bi0 = bias ? bias[col]     : 0.f;
            float bi1 = bias ? bias[col + 1] : 0.f;
            int row0 = bm + wm + (mt << 4) + g;
            if (row0 < M) {
                float2 v = make_float2(acc[mt][nt][0] * scale + bi0,
                                       acc[mt][nt][1] * scale + bi1);
                *(float2*)(C + (long long)row0 * N + col) = v;
            }
            int row1 = row0 + 8;
            if (row1 < M) {
                float2 v = make_float2(acc[mt][nt][2] * scale + bi0,
                                       acc[mt][nt][3] * scale + bi1);
                *(float2*)(C + (long long)row1 * N + col) = v;
            }
        }
    }
}

// ---------------- softmax over rows of length 1024 ----------------
__global__ __launch_bounds__(256)
void softmax_rows(float* __restrict__ attn) {
    long long row = blockIdx.x;
    float* p = attn + row * NTOK;
    int t = threadIdx.x;
    __shared__ float red[8];
    __shared__ float bc;
    float v[4];
    float m = -INFINITY;
#pragma unroll
    for (int i = 0; i < 4; ++i) { v[i] = p[t + i * 256]; m = fmaxf(m, v[i]); }
#pragma unroll
    for (int o = 16; o; o >>= 1) m = fmaxf(m, __shfl_xor_sync(0xffffffffu, m, o));
    if ((t & 31) == 0) red[t >> 5] = m;
    __syncthreads();
    if (t == 0) {
        float mm = red[0];
#pragma unroll
        for (int i = 1; i < 8; ++i) mm = fmaxf(mm, red[i]);
        bc = mm;
    }
    __syncthreads();
    m = bc;
    float s = 0.f;
#pragma unroll
    for (int i = 0; i < 4; ++i) { v[i] = expf(v[i] - m); s += v[i]; }
#pragma unroll
    for (int o = 16; o; o >>= 1) s += __shfl_xor_sync(0xffffffffu, s, o);
    __syncthreads();
    if ((t & 31) == 0) red[t >> 5] = s;
    __syncthreads();
    if (t == 0) {
        float ss = 0.f;
#pragma unroll
        for (int i = 0; i < 8; ++i) ss += red[i];
        bc = 1.0f / ss;
    }
    __syncthreads();
    float inv = bc;
#pragma unroll
    for (int i = 0; i < 4; ++i) p[t + i * 256] = v[i] * inv;
}

// ---------------- GRU gate fusion (slots updated in place) ----------------
__global__ __launch_bounds__(256)
void gru_kernel(float* __restrict__ slots,
                const float* __restrict__ gi, const float* __restrict__ gh) {
    long long idx = (long long)blockIdx.x * 256 + threadIdx.x;
    if (idx >= (long long)ROWS * DIM) return;
    long long r = idx >> 9;
    int c = (int)(idx & (DIM - 1));
    const float* gir = gi + r * (3 * DIM);
    const float* ghr = gh + r * (3 * DIM);
    float ir = gir[c], iz = gir[c + DIM], inn = gir[c + 2 * DIM];
    float hr = ghr[c], hz = ghr[c + DIM], hn  = ghr[c + 2 * DIM];
    float rg = 1.0f / (1.0f + expf(-(ir + hr)));
    float z  = 1.0f / (1.0f + expf(-(iz + hz)));
    float nn = tanhf(inn + rg * hn);
    float h = slots[idx];
    slots[idx] = (1.0f - z) * nn + z * h;
}

// ---------------- finalize: out[row]=sum_d upd; losspart[row]=sum_n attn ----------------
__global__ __launch_bounds__(256)
void finalize_kernel(const float* __restrict__ upd, const float* __restrict__ attn,
                     float* __restrict__ out, float* __restrict__ lp) {
    long long row = blockIdx.x;
    int t = threadIdx.x;
    __shared__ float sh[256];
    const float* ur = upd + row * DIM;
    float s = ur[t] + ur[t + 256];
    sh[t] = s; __syncthreads();
    for (int o = 128; o; o >>= 1) { if (t < o) sh[t] += sh[t + o]; __syncthreads(); }
    if (t == 0) out[row] = sh[0];
    __syncthreads();
    const float* ar = attn + row * NTOK;
    float a = ar[t] + ar[t + 256] + ar[t + 512] + ar[t + 768];
    sh[t] = a; __syncthreads();
    for (int o = 128; o; o >>= 1) { if (t < o) sh[t] += sh[t + o]; __syncthreads(); }
    if (t == 0) lp[row] = sh[0];
}

__global__ __launch_bounds__(256)
void loss_write_kernel(const float* __restrict__ lp, float* __restrict__ out,
                       int out_size) {
    if (out_size <= ROWS) return;
    int t = threadIdx.x;
    __shared__ float sh[256];
    float s = 0.f;
    for (int i = t; i < ROWS; i += 256) s += lp[i];
    sh[t] = s; __syncthreads();
    for (int o = 128; o; o >>= 1) { if (t < o) sh[t] += sh[t + o]; __syncthreads(); }
    if (t == 0) out[ROWS] = sh[0] * (1.0f / ((float)ROWS * (float)NTOK));
}

// ---------------- host ----------------
extern "C" void kernel_launch(void* const* d_in, const int* in_sizes, int n_in,
                              void* d_out, int out_size) {
    const float* inputs   = (const float*)d_in[0];
    const float* inputs_x = (const float*)d_in[1];
    const float* mu       = (const float*)d_in[2];
    const float* sigma    = (const float*)d_in[3];
    const float* qw       = (const float*)d_in[4];
    const float* qb       = (const float*)d_in[5];
    const float* kw       = (const float*)d_in[6];
    const float* kb       = (const float*)d_in[7];
    const float* wih      = (const float*)d_in[8];
    const float* whh      = (const float*)d_in[9];
    const float* bih      = (const float*)d_in[10];
    const float* bhh      = (const float*)d_in[11];
    float* out = (float*)d_out;

    float *slots, *q, *k, *attn, *upd, *gi, *gh, *lp;
    cudaGetSymbolAddress((void**)&slots, g_slots);
    cudaGetSymbolAddress((void**)&q,     g_q);
    cudaGetSymbolAddress((void**)&k,     g_k);
    cudaGetSymbolAddress((void**)&attn,  g_attn);
    cudaGetSymbolAddress((void**)&upd,   g_upd);
    cudaGetSymbolAddress((void**)&gi,    g_gi);
    cudaGetSymbolAddress((void**)&gh,    g_gh);
    cudaGetSymbolAddress((void**)&lp,    g_losspart);

    const float dot_scale = 0.04419417382f;   // 512^-0.5
    const float upd_scale = 1.0f / 512.0f;

    // slots = mu + |sigma| * threefry_normal (partitionable counter scheme)
    init_slots_kernel<<<(NELEM + 255) / 256, 256>>>(mu, sigma);

    // k = inputs @ kw^T + kb   [131072, 512]
    gemm_tf32<true><<<dim3(DIM / 64, BT / 128, 1), 256>>>(
        inputs, kw, kb, k, BT, DIM, DIM, 1.0f, 0, 0, 0);

    for (int it = 0; it < 3; ++it) {
        // q = slots @ qw^T + qb  [12800, 512]
        gemm_tf32<true><<<dim3(DIM / 64, ROWS / 128, 1), 256>>>(
            slots, qw, qb, q, ROWS, DIM, DIM, 1.0f, 0, 0, 0);
        // dots = scale * q @ k^T  per batch: [100,1024]
        gemm_tf32<true><<<dim3(NTOK / 64, 1, BATCH), 256>>>(
            q, k, nullptr, attn, NSLOT, NTOK, DIM, dot_scale,
            (long long)NSLOT * DIM, (long long)NTOK * DIM, (long long)NSLOT * NTOK);
        // softmax over n
        softmax_rows<<<ROWS, 256>>>(attn);
        // updates = (attn @ x) / d  per batch: [100,512]
        gemm_tf32<false><<<dim3(DIM / 64, 1, BATCH), 256>>>(
            attn, inputs_x, nullptr, upd, NSLOT, DIM, NTOK, upd_scale,
            (long long)NSLOT * NTOK, (long long)NTOK * DIM, (long long)NSLOT * DIM);
        // gi = upd @ wih^T + bih ; gh = slots @ whh^T + bhh   [12800, 1536]
        gemm_tf32<true><<<dim3(3 * DIM / 64, ROWS / 128, 1), 256>>>(
            upd, wih, bih, gi, ROWS, 3 * DIM, DIM, 1.0f, 0, 0, 0);
        gemm_tf32<true><<<dim3(3 * DIM / 64, ROWS / 128, 1), 256>>>(
            slots, whh, bhh, gh, ROWS, 3 * DIM, DIM, 1.0f, 0, 0, 0);
        // slots = GRU(upd, slots)
        gru_kernel<<<(ROWS * DIM + 255) / 256, 256>>>(slots, gi, gh);
    }

    finalize_kernel<<<ROWS, 256>>>(upd, attn, out, lp);
    loss_write_kernel<<<1, 256>>>(lp, out, out_size);
}

// round 7
// speedup vs baseline: 3.8648x; 1.0090x over previous
#include <cuda_runtime.h>
#include <math.h>
#include <stdint.h>

#define BATCH 128
#define NTOK  1024
#define DIM   512
#define NSLOT 100
#define ROWS  (BATCH*NSLOT)      /* 12800 */
#define BT    (BATCH*NTOK)       /* 131072 */
#define NELEM (ROWS*DIM)         /* 6553600 */

// ---------------- scratch (static device globals; no allocation) ----------------
__device__ float g_slots[ROWS*DIM];
__device__ float g_q[ROWS*DIM];
__device__ float g_k[(size_t)BT*DIM];
__device__ float g_attn[(size_t)ROWS*NTOK];
__device__ float g_upd[ROWS*DIM];
__device__ float g_gi[(size_t)ROWS*3*DIM];
__device__ float g_gh[(size_t)ROWS*3*DIM];
__device__ float g_losspart[ROWS];

// ---------------- threefry-2x32 (JAX-exact core) ----------------
__device__ __forceinline__ uint32_t rotl32(uint32_t x, int r) {
    return (x << r) | (x >> (32 - r));
}

__device__ __forceinline__ void threefry2x32(uint32_t k0, uint32_t k1,
                                             uint32_t& x0, uint32_t& x1) {
    uint32_t k2 = k0 ^ k1 ^ 0x1BD11BDAu;
    x0 += k0; x1 += k1;
#define TF_RND(r) { x0 += x1; x1 = rotl32(x1, r); x1 ^= x0; }
    TF_RND(13) TF_RND(15) TF_RND(26) TF_RND(6)   x0 += k1; x1 += k2 + 1u;
    TF_RND(17) TF_RND(29) TF_RND(16) TF_RND(24)  x0 += k2; x1 += k0 + 2u;
    TF_RND(13) TF_RND(15) TF_RND(26) TF_RND(6)   x0 += k0; x1 += k1 + 3u;
    TF_RND(17) TF_RND(29) TF_RND(16) TF_RND(24)  x0 += k1; x1 += k2 + 4u;
    TF_RND(13) TF_RND(15) TF_RND(26) TF_RND(6)   x0 += k2; x1 += k0 + 5u;
#undef TF_RND
}

__device__ __forceinline__ float bits_to_normal(uint32_t b) {
    float f  = __uint_as_float((b >> 9) | 0x3f800000u) - 1.0f;
    const float lo = -0.99999994f;
    float u = f * 2.0f + lo;
    u = fmaxf(lo, u);
    return 1.41421356f * erfinvf(u);
}

__global__ void init_slots_kernel(const float* __restrict__ mu,
                                  const float* __restrict__ sigma) {
    int i = blockIdx.x * blockDim.x + threadIdx.x;
    if (i >= NELEM) return;
    uint32_t x0 = 0u, x1 = (uint32_t)i;
    threefry2x32(0u, 1u, x0, x1);
    float nrm = bits_to_normal(x0 ^ x1);
    int c = i & (DIM - 1);
    g_slots[i] = fmaf(fabsf(sigma[c]), nrm, mu[c]);
}

// ---------------- tf32 helpers ----------------
__device__ __forceinline__ uint32_t f2tf(float f) {
    uint32_t r;
    asm("cvt.rna.tf32.f32 %0, %1;" : "=r"(r) : "f"(f));
    return r;
}

__device__ __forceinline__ void mma_tf32(float d[4],
                                         uint32_t a0, uint32_t a1, uint32_t a2, uint32_t a3,
                                         uint32_t b0, uint32_t b1) {
    asm volatile(
        "mma.sync.aligned.m16n8k8.row.col.f32.tf32.tf32.f32 "
        "{%0,%1,%2,%3}, {%4,%5,%6,%7}, {%8,%9}, {%0,%1,%2,%3};"
        : "+f"(d[0]), "+f"(d[1]), "+f"(d[2]), "+f"(d[3])
        : "r"(a0), "r"(a1), "r"(a2), "r"(a3), "r"(b0), "r"(b1));
}

// ---------------- tf32 tensor-core GEMM, double-buffered ----------------
// C[M,N] = scale * A[M,K] @ op(B) + bias
// TRANSB=true : B is [N,K] row-major (NT);  TRANSB=false: B is [K,N] row-major (NN)
// Block tile 128x64, K-chunk 32; 8 warps 4(m)x2(n), warp tile 32x32.
// K % 32 == 0, N % 64 == 0; M guarded. Dynamic smem: 2 stages.
#define AS_OFF(b,r,c) ((b)*(128*36) + (r)*36 + (c))
#define BS_OFF(b,r,c) (2*(128*36) + (b)*(64*36) + (r)*36 + (c))
#define GEMM_SMEM_BYTES ((2*128*36 + 2*64*36) * 4)

template <bool TRANSB>
__global__ __launch_bounds__(256)
void gemm_tf32(const float* __restrict__ A, const float* __restrict__ B,
               const float* __restrict__ bias, float* __restrict__ C,
               int M, int N, int K, float scale,
               long long strA, long long strB, long long strC) {
    extern __shared__ uint32_t sm[];
    A += (long long)blockIdx.z * strA;
    B += (long long)blockIdx.z * strB;
    C += (long long)blockIdx.z * strC;
    const int bm = blockIdx.y << 7;
    const int bn = blockIdx.x << 6;

    const int tid  = threadIdx.x;
    const int lane = tid & 31;
    const int wid  = tid >> 5;
    const int wm = (wid & 3) << 5;
    const int wn = (wid >> 2) << 5;
    const int g  = lane >> 2;
    const int tg = lane & 3;

    // A-load coords: idx = tid + i*256 -> row 0..127, c4 0..28 step 4
    // B-load (NT): idx = tid + i*256 -> row 0..63, c4
    // B-load (NN): kr = idx>>4 (0..31), nc = (idx&15)<<2

    float acc[2][4][4];
#pragma unroll
    for (int mt = 0; mt < 2; ++mt)
#pragma unroll
        for (int nt = 0; nt < 4; ++nt)
#pragma unroll
            for (int e = 0; e < 4; ++e) acc[mt][nt][e] = 0.f;

    const int nch = K >> 5;

    // ---- prologue: chunk 0 -> stage 0 ----
    {
#pragma unroll
        for (int i = 0; i < 4; ++i) {
            int idx = tid + (i << 8);
            int row = idx >> 3;
            int c4  = (idx & 7) << 2;
            float4 v;
            if (bm + row < M)
                v = *(const float4*)(A + (long long)(bm + row) * K + c4);
            else
                v = make_float4(0.f, 0.f, 0.f, 0.f);
            sm[AS_OFF(0, row, c4 + 0)] = f2tf(v.x);
            sm[AS_OFF(0, row, c4 + 1)] = f2tf(v.y);
            sm[AS_OFF(0, row, c4 + 2)] = f2tf(v.z);
            sm[AS_OFF(0, row, c4 + 3)] = f2tf(v.w);
        }
        if (TRANSB) {
#pragma unroll
            for (int i = 0; i < 2; ++i) {
                int idx = tid + (i << 8);
                int row = idx >> 3;
                int c4  = (idx & 7) << 2;
                float4 v = *(const float4*)(B + (long long)(bn + row) * K + c4);
                sm[BS_OFF(0, row, c4 + 0)] = f2tf(v.x);
                sm[BS_OFF(0, row, c4 + 1)] = f2tf(v.y);
                sm[BS_OFF(0, row, c4 + 2)] = f2tf(v.z);
                sm[BS_OFF(0, row, c4 + 3)] = f2tf(v.w);
            }
        } else {
#pragma unroll
            for (int i = 0; i < 2; ++i) {
                int idx = tid + (i << 8);
                int kr  = idx >> 4;
                int nc  = (idx & 15) << 2;
                float4 v = *(const float4*)(B + (long long)kr * N + bn + nc);
                sm[BS_OFF(0, nc + 0, kr)] = f2tf(v.x);
                sm[BS_OFF(0, nc + 1, kr)] = f2tf(v.y);
                sm[BS_OFF(0, nc + 2, kr)] = f2tf(v.z);
                sm[BS_OFF(0, nc + 3, kr)] = f2tf(v.w);
            }
        }
    }
    __syncthreads();

    for (int c = 0; c < nch; ++c) {
        const int cur = c & 1, nxt = cur ^ 1;
        const bool hn = (c + 1 < nch);
        const int k0n = (c + 1) << 5;

        // ---- issue next chunk's global loads (latency overlapped with mma) ----
        float4 av[4], bv[2];
        if (hn) {
#pragma unroll
            for (int i = 0; i < 4; ++i) {
                int idx = tid + (i << 8);
                int row = idx >> 3;
                int c4  = (idx & 7) << 2;
                if (bm + row < M)
                    av[i] = *(const float4*)(A + (long long)(bm + row) * K + k0n + c4);
                else
                    av[i] = make_float4(0.f, 0.f, 0.f, 0.f);
            }
            if (TRANSB) {
#pragma unroll
                for (int i = 0; i < 2; ++i) {
                    int idx = tid + (i << 8);
                    int row = idx >> 3;
                    int c4  = (idx & 7) << 2;
                    bv[i] = *(const float4*)(B + (long long)(bn + row) * K + k0n + c4);
                }
            } else {
#pragma unroll
                for (int i = 0; i < 2; ++i) {
                    int idx = tid + (i << 8);
                    int kr  = idx >> 4;
                    int nc  = (idx & 15) << 2;
                    bv[i] = *(const float4*)(B + (long long)(k0n + kr) * N + bn + nc);
                }
            }
        }

        // ---- mma on current stage ----
#pragma unroll
        for (int ks = 0; ks < 4; ++ks) {
            const int k8 = ks << 3;
            uint32_t a[2][4], b[4][2];
#pragma unroll
            for (int mt = 0; mt < 2; ++mt) {
                int r = wm + (mt << 4);
                a[mt][0] = sm[AS_OFF(cur, r + g,     k8 + tg)];
                a[mt][1] = sm[AS_OFF(cur, r + 8 + g, k8 + tg)];
                a[mt][2] = sm[AS_OFF(cur, r + g,     k8 + tg + 4)];
                a[mt][3] = sm[AS_OFF(cur, r + 8 + g, k8 + tg + 4)];
            }
#pragma unroll
            for (int nt = 0; nt < 4; ++nt) {
                int cc = wn + (nt << 3);
                b[nt][0] = sm[BS_OFF(cur, cc + g, k8 + tg)];
                b[nt][1] = sm[BS_OFF(cur, cc + g, k8 + tg + 4)];
            }
#pragma unroll
            for (int mt = 0; mt < 2; ++mt)
#pragma unroll
                for (int nt = 0; nt < 4; ++nt)
                    mma_tf32(acc[mt][nt], a[mt][0], a[mt][1], a[mt][2], a[mt][3],
                             b[nt][0], b[nt][1]);
        }

        // ---- convert + store next stage ----
        if (hn) {
#pragma unroll
            for (int i = 0; i < 4; ++i) {
                int idx = tid + (i << 8);
                int row = idx >> 3;
                int c4  = (idx & 7) << 2;
                sm[AS_OFF(nxt, row, c4 + 0)] = f2tf(av[i].x);
                sm[AS_OFF(nxt, row, c4 + 1)] = f2tf(av[i].y);
                sm[AS_OFF(nxt, row, c4 + 2)] = f2tf(av[i].z);
                sm[AS_OFF(nxt, row, c4 + 3)] = f2tf(av[i].w);
            }
            if (TRANSB) {
#pragma unroll
                for (int i = 0; i < 2; ++i) {
                    int idx = tid + (i << 8);
                    int row = idx >> 3;
                    int c4  = (idx & 7) << 2;
                    sm[BS_OFF(nxt, row, c4 + 0)] = f2tf(bv[i].x);
                    sm[BS_OFF(nxt, row, c4 + 1)] = f2tf(bv[i].y);
                    sm[BS_OFF(nxt, row, c4 + 2)] = f2tf(bv[i].z);
                    sm[BS_OFF(nxt, row, c4 + 3)] = f2tf(bv[i].w);
                }
            } else {
#pragma unroll
                for (int i = 0; i < 2; ++i) {
                    int idx = tid + (i << 8);
                    int kr  = idx >> 4;
                    int nc  = (idx & 15) << 2;
                    sm[BS_OFF(nxt, nc + 0, kr)] = f2tf(bv[i].x);
                    sm[BS_OFF(nxt, nc + 1, kr)] = f2tf(bv[i].y);
                    sm[BS_OFF(nxt, nc + 2, kr)] = f2tf(bv[i].z);
                    sm[BS_OFF(nxt, nc + 3, kr)] = f2tf(bv[i].w);
                }
            }
        }
        __syncthreads();
    }

    // ---- epilogue ----
#pragma unroll
    for (int mt = 0; mt < 2; ++mt) {
#pragma unroll
        for (int nt = 0; nt < 4; ++nt) {
            int col = bn + wn + (nt << 3) + (tg << 1);
            float bi0 = bias ? bias[col]     : 0.f;
            float bi1 = bias ? bias[col + 1] : 0.f;
            int row0 = bm + wm + (mt << 4) + g;
            if (row0 < M) {
                float2 v = make_float2(acc[mt][nt][0] * scale + bi0,
                                       acc[mt][nt][1] * scale + bi1);
                *(float2*)(C + (long long)row0 * N + col) = v;
            }
            int row1 = row0 + 8;
            if (row1 < M) {
                float2 v = make_float2(acc[mt][nt][2] * scale + bi0,
                                       acc[mt][nt][3] * scale + bi1);
                *(float2*)(C + (long long)row1 * N + col) = v;
            }
        }
    }
}

// ---------------- softmax over rows of length 1024 ----------------
__global__ __launch_bounds__(256)
void softmax_rows(float* __restrict__ attn) {
    long long row = blockIdx.x;
    float* p = attn + row * NTOK;
    int t = threadIdx.x;
    __shared__ float red[8];
    __shared__ float bc;
    float v[4];
    float m = -INFINITY;
#pragma unroll
    for (int i = 0; i < 4; ++i) { v[i] = p[t + i * 256]; m = fmaxf(m, v[i]); }
#pragma unroll
    for (int o = 16; o; o >>= 1) m = fmaxf(m, __shfl_xor_sync(0xffffffffu, m, o));
    if ((t & 31) == 0) red[t >> 5] = m;
    __syncthreads();
    if (t == 0) {
        float mm = red[0];
#pragma unroll
        for (int i = 1; i < 8; ++i) mm = fmaxf(mm, red[i]);
        bc = mm;
    }
    __syncthreads();
    m = bc;
    float s = 0.f;
#pragma unroll
    for (int i = 0; i < 4; ++i) { v[i] = expf(v[i] - m); s += v[i]; }
#pragma unroll
    for (int o = 16; o; o >>= 1) s += __shfl_xor_sync(0xffffffffu, s, o);
    __syncthreads();
    if ((t & 31) == 0) red[t >> 5] = s;
    __syncthreads();
    if (t == 0) {
        float ss = 0.f;
#pragma unroll
        for (int i = 0; i < 8; ++i) ss += red[i];
        bc = 1.0f / ss;
    }
    __syncthreads();
    float inv = bc;
#pragma unroll
    for (int i = 0; i < 4; ++i) p[t + i * 256] = v[i] * inv;
}

// ---------------- GRU gate fusion (slots updated in place) ----------------
__global__ __launch_bounds__(256)
void gru_kernel(float* __restrict__ slots,
                const float* __restrict__ gi, const float* __restrict__ gh) {
    long long idx = (long long)blockIdx.x * 256 + threadIdx.x;
    if (idx >= (long long)ROWS * DIM) return;
    long long r = idx >> 9;
    int c = (int)(idx & (DIM - 1));
    const float* gir = gi + r * (3 * DIM);
    const float* ghr = gh + r * (3 * DIM);
    float ir = gir[c], iz = gir[c + DIM], inn = gir[c + 2 * DIM];
    float hr = ghr[c], hz = ghr[c + DIM], hn  = ghr[c + 2 * DIM];
    float rg = 1.0f / (1.0f + expf(-(ir + hr)));
    float z  = 1.0f / (1.0f + expf(-(iz + hz)));
    float nn = tanhf(inn + rg * hn);
    float h = slots[idx];
    slots[idx] = (1.0f - z) * nn + z * h;
}

// ---------------- finalize: out[row]=sum_d upd; losspart[row]=sum_n attn ----------------
__global__ __launch_bounds__(256)
void finalize_kernel(const float* __restrict__ upd, const float* __restrict__ attn,
                     float* __restrict__ out, float* __restrict__ lp) {
    long long row = blockIdx.x;
    int t = threadIdx.x;
    __shared__ float sh[256];
    const float* ur = upd + row * DIM;
    float s = ur[t] + ur[t + 256];
    sh[t] = s; __syncthreads();
    for (int o = 128; o; o >>= 1) { if (t < o) sh[t] += sh[t + o]; __syncthreads(); }
    if (t == 0) out[row] = sh[0];
    __syncthreads();
    const float* ar = attn + row * NTOK;
    float a = ar[t] + ar[t + 256] + ar[t + 512] + ar[t + 768];
    sh[t] = a; __syncthreads();
    for (int o = 128; o; o >>= 1) { if (t < o) sh[t] += sh[t + o]; __syncthreads(); }
    if (t == 0) lp[row] = sh[0];
}

__global__ __launch_bounds__(256)
void loss_write_kernel(const float* __restrict__ lp, float* __restrict__ out,
                       int out_size) {
    if (out_size <= ROWS) return;
    int t = threadIdx.x;
    __shared__ float sh[256];
    float s = 0.f;
    for (int i = t; i < ROWS; i += 256) s += lp[i];
    sh[t] = s; __syncthreads();
    for (int o = 128; o; o >>= 1) { if (t < o) sh[t] += sh[t + o]; __syncthreads(); }
    if (t == 0) out[ROWS] = sh[0] * (1.0f / ((float)ROWS * (float)NTOK));
}

// ---------------- host ----------------
extern "C" void kernel_launch(void* const* d_in, const int* in_sizes, int n_in,
                              void* d_out, int out_size) {
    const float* inputs   = (const float*)d_in[0];
    const float* inputs_x = (const float*)d_in[1];
    const float* mu       = (const float*)d_in[2];
    const float* sigma    = (const float*)d_in[3];
    const float* qw       = (const float*)d_in[4];
    const float* qb       = (const float*)d_in[5];
    const float* kw       = (const float*)d_in[6];
    const float* kb       = (const float*)d_in[7];
    const float* wih      = (const float*)d_in[8];
    const float* whh      = (const float*)d_in[9];
    const float* bih      = (const float*)d_in[10];
    const float* bhh      = (const float*)d_in[11];
    float* out = (float*)d_out;

    float *slots, *q, *k, *attn, *upd, *gi, *gh, *lp;
    cudaGetSymbolAddress((void**)&slots, g_slots);
    cudaGetSymbolAddress((void**)&q,     g_q);
    cudaGetSymbolAddress((void**)&k,     g_k);
    cudaGetSymbolAddress((void**)&attn,  g_attn);
    cudaGetSymbolAddress((void**)&upd,   g_upd);
    cudaGetSymbolAddress((void**)&gi,    g_gi);
    cudaGetSymbolAddress((void**)&gh,    g_gh);
    cudaGetSymbolAddress((void**)&lp,    g_losspart);

    cudaFuncSetAttribute(gemm_tf32<true>,
                         cudaFuncAttributeMaxDynamicSharedMemorySize, GEMM_SMEM_BYTES);
    cudaFuncSetAttribute(gemm_tf32<false>,
                         cudaFuncAttributeMaxDynamicSharedMemorySize, GEMM_SMEM_BYTES);

    const float dot_scale = 0.04419417382f;   // 512^-0.5
    const float upd_scale = 1.0f / 512.0f;

    // slots = mu + |sigma| * threefry_normal (partitionable counter scheme)
    init_slots_kernel<<<(NELEM + 255) / 256, 256>>>(mu, sigma);

    // k = inputs @ kw^T + kb   [131072, 512]
    gemm_tf32<true><<<dim3(DIM / 64, BT / 128, 1), 256, GEMM_SMEM_BYTES>>>(
        inputs, kw, kb, k, BT, DIM, DIM, 1.0f, 0, 0, 0);

    for (int it = 0; it < 3; ++it) {
        // q = slots @ qw^T + qb  [12800, 512]
        gemm_tf32<true><<<dim3(DIM / 64, ROWS / 128, 1), 256, GEMM_SMEM_BYTES>>>(
            slots, qw, qb, q, ROWS, DIM, DIM, 1.0f, 0, 0, 0);
        // dots = scale * q @ k^T  per batch: [100,1024]
        gemm_tf32<true><<<dim3(NTOK / 64, 1, BATCH), 256, GEMM_SMEM_BYTES>>>(
            q, k, nullptr, attn, NSLOT, NTOK, DIM, dot_scale,
            (long long)NSLOT * DIM, (long long)NTOK * DIM, (long long)NSLOT * NTOK);
        // softmax over n
        softmax_rows<<<ROWS, 256>>>(attn);
        // updates = (attn @ x) / d  per batch: [100,512]
        gemm_tf32<false><<<dim3(DIM / 64, 1, BATCH), 256, GEMM_SMEM_BYTES>>>(
            attn, inputs_x, nullptr, upd, NSLOT, DIM, NTOK, upd_scale,
            (long long)NSLOT * NTOK, (long long)NTOK * DIM, (long long)NSLOT * DIM);
        // gi = upd @ wih^T + bih ; gh = slots @ whh^T + bhh   [12800, 1536]
        gemm_tf32<true><<<dim3(3 * DIM / 64, ROWS / 128, 1), 256, GEMM_SMEM_BYTES>>>(
            upd, wih, bih, gi, ROWS, 3 * DIM, DIM, 1.0f, 0, 0, 0);
        gemm_tf32<true><<<dim3(3 * DIM / 64, ROWS / 128, 1), 256, GEMM_SMEM_BYTES>>>(
            slots, whh, bhh, gh, ROWS, 3 * DIM, DIM, 1.0f, 0, 0, 0);
        // slots = GRU(upd, slots)
        gru_kernel<<<(ROWS * DIM + 255) / 256, 256>>>(slots, gi, gh);
    }

    finalize_kernel<<<ROWS, 256>>>(upd, attn, out, lp);
    loss_write_kernel<<<1, 256>>>(lp, out, out_size);
}